// round 16
// baseline (speedup 1.0000x reference)
#include <cuda_runtime.h>
#include <cstdint>

// RenderLoss: B=262144 batches x MAXC=13 corners.
// R13: 2 tiles per warp (bid, bid+2048), ALL global loads front-loaded
// (14 LDG.128 + 2 LDG.32 in flight) so input latency is exposed once per
// two tiles. Per-warp smem: OUT region 4992B (y-lanes zeroed once, x/z
// staged per tile, cp.async.bulk to gmem) + IN region 3328B (in0 then in1).
// Corner math: packed-f32x2 Horner for sin/cos(lat) (FMA pipe), MUFU only
// for sincos(lon) + rsqrt. Edge math scalar (short chain). ratio input
// cancels under the final normalization -> unused.

constexpr int BATCH = 262144;
constexpr int MAXC  = 13;
constexpr int TPB   = 64;                   // 2 warps per block
constexpr int WPB   = TPB / 32;
constexpr int GRID  = 2048;                 // each block: tiles bid, bid+2048
constexpr int OUTF  = 32 * MAXC * 3;        // 1248 floats (4992 B)
constexpr int INF   = 32 * MAXC * 2;        // 832 floats (3328 B)
constexpr int WREG  = OUTF + INF;           // 2080 floats per warp
constexpr int IN_F4  = INF / 4;             // 208
constexpr int OUT_F4 = OUTF / 4;            // 312

__device__ __forceinline__ uint32_t smem_u32(const void* p) {
    uint32_t a;
    asm("{ .reg .u64 t; cvta.to.shared.u64 t, %1; cvt.u32.u64 %0, t; }"
        : "=r"(a) : "l"(p));
    return a;
}
using ull = unsigned long long;
__device__ __forceinline__ ull pk2(float lo, float hi) {
    ull r; asm("mov.b64 %0, {%1, %2};" : "=l"(r) : "f"(lo), "f"(hi)); return r;
}
__device__ __forceinline__ void upk2(ull v, float& lo, float& hi) {
    asm("mov.b64 {%0, %1}, %2;" : "=f"(lo), "=f"(hi) : "l"(v));
}
__device__ __forceinline__ ull fma2(ull a, ull b, ull c) {
    ull d; asm("fma.rn.f32x2 %0, %1, %2, %3;" : "=l"(d) : "l"(a), "l"(b), "l"(c));
    return d;
}

struct Corner { float a, b, s; };   // a=sin(lon)cos(lat), b=cos(lon)cos(lat), s=sin(lat)

__device__ __forceinline__ Corner corner_eval(float2 ll) {
    Corner r;
    float so, co;
    __sincosf(ll.x, &so, &co);                  // lon (MUFU)
    const float t2 = ll.y * ll.y;
    const ull t22 = pk2(t2, t2);
    ull p = fma2(t22, pk2(-2.5052108e-8f, -2.7557319e-7f),
                      pk2( 2.7557319e-6f,  2.4801587e-5f));
    p = fma2(t22, p,  pk2(-1.9841270e-4f, -1.3888889e-3f));
    p = fma2(t22, p,  pk2( 8.3333333e-3f,  4.1666667e-2f));
    p = fma2(t22, p,  pk2(-0.16666667f,   -0.5f));
    p = fma2(t22, p,  pk2(1.0f, 1.0f));         // {sin(y)/y, cos(y)}
    float sy, cl;
    upk2(p, sy, cl);
    r.s = ll.y * sy;
    r.a = so * cl;
    r.b = co * cl;
    return r;
}

// Compute 13 edge normals for this lane's batch and stage x/z into ob
// (y-slots pre-zeroed). Scalar edge chain (short path to rsqrt).
__device__ __forceinline__ void compute_tile(const float2* __restrict__ c,
                                             int num, float* __restrict__ ob) {
    Corner c0 = corner_eval(c[0]);
    Corner cur = c0;
    float n0x = 0.f, n0z = 0.f;
    #pragma unroll
    for (int j = 0; j < MAXC; j++) {
        Corner nxt = c0;                        // safe default (used when j=12)
        if (j + 1 < MAXC) nxt = corner_eval(c[j + 1]);

        const bool wrap  = (j + 1 == num);
        const bool valid = (j < num);

        const float ta = wrap ? c0.a : nxt.a;
        const float tb = wrap ? c0.b : nxt.b;
        const float ts = wrap ? c0.s : nxt.s;

        // Edge scaled by positive cur.s*ts -> direction preserved.
        float vx = valid ? fmaf(cur.a, ts, -ta * cur.s) : 1.0f;
        float vz = valid ? fmaf(cur.b, ts, -tb * cur.s) : 0.0f;

        const float rn = rsqrtf(fmaf(vx, vx, vz * vz));
        const float nx = -vz * rn;
        const float nz =  vx * rn;

        if (j == 0) { n0x = nx; n0z = nz; }     // num>=4 -> edge 0 always valid

        ob[3 * j + 0] = valid ? nx : ((j == num) ? n0x : 0.0f);
        ob[3 * j + 2] = valid ? nz : ((j == num) ? n0z : 0.0f);

        cur = nxt;
    }
}

__global__ __launch_bounds__(TPB) void render_loss_kernel(
    const float* __restrict__ gt,      // [B,13,2] lon,lat
    const int*   __restrict__ nums,    // [B]
    float*       __restrict__ out)     // [B,13,3]
{
    __shared__ __align__(16) float smf[WPB * WREG];  // 16640 B
    const int t = threadIdx.x;
    const int w = t >> 5;
    const int l = t & 31;
    float* obuf = smf + w * WREG;        // OUT region [0, 1248)
    float* ibuf = obuf + OUTF;           // IN  region [1248, 2080)

    const int wb0 = blockIdx.x * TPB + w * 32;       // tile0 batch base
    const int wb1 = wb0 + GRID * TPB;                // tile1 batch base

    // ---- Front-load ALL global reads (MLP 16) ----
    const float4* g0 = reinterpret_cast<const float4*>(gt + (size_t)wb0 * (MAXC * 2));
    const float4* g1 = reinterpret_cast<const float4*>(gt + (size_t)wb1 * (MAXC * 2));
    float4 r0[7], r1[7];
    #pragma unroll
    for (int i = 0; i < 7; i++) {
        int idx = l + i * 32;
        if (idx < IN_F4) { r0[i] = g0[idx]; r1[i] = g1[idx]; }
    }
    const int num0 = nums[wb0 + l];
    const int num1 = nums[wb1 + l];

    // ---- Stage in0; zero OUT y-lanes (and everything else) once ----
    float4* ib4 = reinterpret_cast<float4*>(ibuf);
    #pragma unroll
    for (int i = 0; i < 7; i++) {
        int idx = l + i * 32;
        if (idx < IN_F4) ib4[idx] = r0[i];
    }
    float4* ob4 = reinterpret_cast<float4*>(obuf);
    #pragma unroll
    for (int i = 0; i < 10; i++) {
        int idx = l + i * 32;
        if (idx < OUT_F4) ob4[idx] = make_float4(0.f, 0.f, 0.f, 0.f);
    }
    __syncwarp();

    // ---- Tile 0: preload c0, release IN to tile1's staging ----
    float2 c0[MAXC];
    {
        const float2* cp = reinterpret_cast<const float2*>(ibuf + l * (MAXC * 2));
        #pragma unroll
        for (int j = 0; j < MAXC; j++) c0[j] = cp[j];
    }
    __syncwarp();                        // all lanes done reading in0
    #pragma unroll
    for (int i = 0; i < 7; i++) {        // stage in1 now (frees r1 registers)
        int idx = l + i * 32;
        if (idx < IN_F4) ib4[idx] = r1[i];
    }

    compute_tile(c0, num0, obuf + l * (MAXC * 3));   // stride 39: conflict-free
    __syncwarp();                        // staging + in1 STS complete warp-wide

    if (l == 0) {
        asm volatile("fence.proxy.async.shared::cta;" ::: "memory");
        float* gdst = out + (size_t)wb0 * (MAXC * 3);
        asm volatile(
            "cp.async.bulk.global.shared::cta.bulk_group [%0], [%1], %2;"
            :: "l"(gdst), "r"(smem_u32(obuf)), "r"(OUTF * 4) : "memory");
        asm volatile("cp.async.bulk.commit_group;" ::: "memory");
    }

    // ---- Tile 1: preload c1 (covers the bulk-store smem-read window) ----
    float2 c1[MAXC];
    {
        const float2* cp = reinterpret_cast<const float2*>(ibuf + l * (MAXC * 2));
        #pragma unroll
        for (int j = 0; j < MAXC; j++) c1[j] = cp[j];
    }
    if (l == 0) {                        // OUT must be free before restaging
        asm volatile("cp.async.bulk.wait_group 0;" ::: "memory");
    }
    __syncwarp();                        // all lanes behind lane0's wait

    compute_tile(c1, num1, obuf + l * (MAXC * 3));
    __syncwarp();

    if (l == 0) {
        asm volatile("fence.proxy.async.shared::cta;" ::: "memory");
        float* gdst = out + (size_t)wb1 * (MAXC * 3);
        asm volatile(
            "cp.async.bulk.global.shared::cta.bulk_group [%0], [%1], %2;"
            :: "l"(gdst), "r"(smem_u32(obuf)), "r"(OUTF * 4) : "memory");
        asm volatile("cp.async.bulk.commit_group;" ::: "memory");
        asm volatile("cp.async.bulk.wait_group 0;" ::: "memory");
    }
}

extern "C" void kernel_launch(void* const* d_in, const int* in_sizes, int n_in,
                              void* d_out, int out_size)
{
    const float* gt    = (const float*)d_in[0];  // GT_up [B,13,2] f32
    const int*   nums  = (const int*)  d_in[1];  // corner_nums [B] i32
    // d_in[2] (up_down_ratio) cancels under normalization -> unused.
    float*       outp  = (float*)d_out;          // [B,13,3] f32

    render_loss_kernel<<<GRID, TPB>>>(gt, nums, outp);
}